// round 3
// baseline (speedup 1.0000x reference)
#include <cuda_runtime.h>
#include <cstdint>

// Problem constants
#define BATCH 512
#define INF   4096
#define OUTF  4096

// GEMM tiling: CTA 128x128, K-chunk 32 fp32. Warp grid 2(M) x 4(N), warp tile 64x32.
#define TM 128
#define TN 128
#define KC 32
#define ITERS (INF / KC)          // 128
#define STAGES 3
#define AS_STRIDE 36              // 32 + 4 pad floats -> conflict-free fragment LDS
#define TILE_FLOATS (128 * AS_STRIDE)           // 4608 floats = 18432 B
#define STAGE_BYTES (2 * TILE_FLOATS * 4)       // A + B = 36864 B
#define SMEM_BYTES (STAGES * STAGE_BYTES)       // 110592 B

// Scratch (device globals are the sanctioned scratch mechanism)
__device__ float g_W[(size_t)OUTF * INF];   // dequantized weight, tf32-rounded (64 MB)
__device__ float g_x[(size_t)BATCH * INF];  // x, tf32-rounded (8 MB)

// ---------------- PTX helpers (ALL plain-sm_103 legal: no tcgen05 / no 'a' features) ----
__device__ __forceinline__ uint32_t smem_u32(const void* p) {
    uint32_t a;
    asm("{ .reg .u64 t; cvta.to.shared.u64 t, %1; cvt.u32.u64 %0, t; }" : "=r"(a) : "l"(p));
    return a;
}

#define CP_ASYNC16(dst_smem, src_gmem) \
    asm volatile("cp.async.cg.shared.global [%0], [%1], 16;" \
                 :: "r"((uint32_t)(dst_smem)), "l"(src_gmem) : "memory")
#define CP_COMMIT() asm volatile("cp.async.commit_group;" ::: "memory")
#define CP_WAIT(n)  asm volatile("cp.async.wait_group %0;" :: "n"(n) : "memory")

// mma.sync m16n8k8 tf32 (sm_80+ baseline feature)
#define MMA_TF32(d, a, b) \
    asm volatile( \
        "mma.sync.aligned.m16n8k8.row.col.f32.tf32.tf32.f32 " \
        "{%0,%1,%2,%3}, {%4,%5,%6,%7}, {%8,%9}, {%0,%1,%2,%3};" \
        : "+f"((d)[0]), "+f"((d)[1]), "+f"((d)[2]), "+f"((d)[3]) \
        : "r"((a)[0]), "r"((a)[1]), "r"((a)[2]), "r"((a)[3]), \
          "r"((b)[0]), "r"((b)[1]))

__device__ __forceinline__ float tf32_rn(float x) {
    uint32_t b;
    asm("cvt.rna.tf32.f32 %0, %1;" : "=r"(b) : "f"(x));
    return __uint_as_float(b);
}

__device__ __forceinline__ float scale_from_exponent(const int* e) {
    int iv = *e;
    // exponent may arrive as int32 or as float32 bit pattern
    if (iv > -1000000 && iv < 1000000) return exp2f((float)iv);
    return exp2f(__int_as_float(iv));
}

// ---------------- kernel 1: dequant W = (U @ t_hat), tf32-rounded ----------------
// U: [OUT*IN, 4] fp32 row-major => one float4 per W element. Each thread: 4 W elems.
__global__ void __launch_bounds__(256) prep_w_kernel(
    const float4* __restrict__ U4, const float* __restrict__ q, const int* __restrict__ e)
{
    float sc = scale_from_exponent(e) * (1.0f / 7.0f);
    float t0 = q[0] * sc, t1 = q[1] * sc, t2 = q[2] * sc, t3 = q[3] * sc;

    size_t t = (size_t)blockIdx.x * 256 + threadIdx.x;   // 0 .. 4194303
    const float4* u = U4 + (t << 2);
    float4 a = u[0], b = u[1], c = u[2], d = u[3];
    float4 r;
    r.x = tf32_rn(fmaf(a.x, t0, fmaf(a.y, t1, fmaf(a.z, t2, a.w * t3))));
    r.y = tf32_rn(fmaf(b.x, t0, fmaf(b.y, t1, fmaf(b.z, t2, b.w * t3))));
    r.z = tf32_rn(fmaf(c.x, t0, fmaf(c.y, t1, fmaf(c.z, t2, c.w * t3))));
    r.w = tf32_rn(fmaf(d.x, t0, fmaf(d.y, t1, fmaf(d.z, t2, d.w * t3))));
    reinterpret_cast<float4*>(g_W)[t] = r;
}

// ---------------- kernel 2: round x to tf32 ----------------
__global__ void __launch_bounds__(256) round_x_kernel(const float4* __restrict__ x4)
{
    size_t i = (size_t)blockIdx.x * 256 + threadIdx.x;   // 0 .. 524287
    float4 v = x4[i];
    v.x = tf32_rn(v.x); v.y = tf32_rn(v.y); v.z = tf32_rn(v.z); v.w = tf32_rn(v.w);
    reinterpret_cast<float4*>(g_x)[i] = v;
}

// ---------------- kernel 3: tf32 mma.sync GEMM: y = x @ W^T + b ----------------
// A = g_x [512,4096] row-major (M,K). B = g_W [4096,4096] row-major (N,K).
// Both K-major => mma row.col fits directly.
__global__ void __launch_bounds__(256, 1) gemm_tf32_kernel(
    const float* __restrict__ bias, float* __restrict__ out)
{
    extern __shared__ float smf[];
    const uint32_t sb = smem_u32(smf);
    const int tid  = threadIdx.x;
    const int wid  = tid >> 5;
    const int lane = tid & 31;
    const int g    = lane >> 2;       // groupID
    const int t    = lane & 3;        // thread-in-group
    const int wrow = wid >> 2;        // 0..1 (M)
    const int wcol = wid & 3;         // 0..3 (N)
    const int m0 = blockIdx.y * TM;
    const int n0 = blockIdx.x * TN;

    const float* Ag = g_x + (size_t)m0 * INF;
    const float* Bg = g_W + (size_t)n0 * INF;

    float acc[4][4][4];
    #pragma unroll
    for (int i = 0; i < 4; ++i)
        #pragma unroll
        for (int j = 0; j < 4; ++j)
            #pragma unroll
            for (int k = 0; k < 4; ++k) acc[i][j][k] = 0.f;

    // Per-thread cp.async source/dest offsets: cid = i*256+tid; row = cid/8, seg = cid%8
    // A tile rows 0..127 (M), B tile rows 0..127 (N); row stride in smem = 36 floats.
    auto load_stage = [&](int it, int s) {
        const uint32_t As = sb + (uint32_t)s * STAGE_BYTES;
        const uint32_t Bs = As + TILE_FLOATS * 4;
        const int kbase = it * KC;
        #pragma unroll
        for (int i = 0; i < 4; ++i) {
            int cid = i * 256 + tid;
            int r = cid >> 3, c = cid & 7;
            CP_ASYNC16(As + (uint32_t)(r * AS_STRIDE + c * 4) * 4,
                       Ag + (size_t)r * INF + kbase + c * 4);
        }
        #pragma unroll
        for (int i = 0; i < 4; ++i) {
            int cid = i * 256 + tid;
            int r = cid >> 3, c = cid & 7;
            CP_ASYNC16(Bs + (uint32_t)(r * AS_STRIDE + c * 4) * 4,
                       Bg + (size_t)r * INF + kbase + c * 4);
        }
        CP_COMMIT();
    };

    #pragma unroll
    for (int s = 0; s < STAGES - 1; ++s) load_stage(s, s);

    // warp fragment bases (float indices into smem)
    const int a_warp = wrow * 64;            // A row base for this warp
    const int b_warp = wcol * 32;            // B row base for this warp

    #pragma unroll 1
    for (int it = 0; it < ITERS; ++it) {
        CP_WAIT(STAGES - 2);
        __syncthreads();
        int nxt = it + STAGES - 1;
        if (nxt < ITERS) load_stage(nxt, nxt % STAGES);

        const float* As = smf + (size_t)(it % STAGES) * (STAGE_BYTES / 4);
        const float* Bs = As + TILE_FLOATS;

        #pragma unroll
        for (int ks = 0; ks < 4; ++ks) {
            const int k0 = ks * 8;
            uint32_t a[4][4], b[4][2];
            #pragma unroll
            for (int mt = 0; mt < 4; ++mt) {
                const float* ab = As + (a_warp + mt * 16 + g) * AS_STRIDE + k0 + t;
                a[mt][0] = __float_as_uint(ab[0]);
                a[mt][1] = __float_as_uint(ab[8 * AS_STRIDE]);
                a[mt][2] = __float_as_uint(ab[4]);
                a[mt][3] = __float_as_uint(ab[8 * AS_STRIDE + 4]);
            }
            #pragma unroll
            for (int nt = 0; nt < 4; ++nt) {
                const float* bb = Bs + (b_warp + nt * 8 + g) * AS_STRIDE + k0 + t;
                b[nt][0] = __float_as_uint(bb[0]);
                b[nt][1] = __float_as_uint(bb[4]);
            }
            #pragma unroll
            for (int mt = 0; mt < 4; ++mt)
                #pragma unroll
                for (int nt = 0; nt < 4; ++nt)
                    MMA_TF32(acc[mt][nt], a[mt], b[nt]);
        }
        __syncthreads();
    }

    // ---- epilogue: registers -> gmem with fused bias, float2 stores ----
    #pragma unroll
    for (int nt = 0; nt < 4; ++nt) {
        const int n = n0 + b_warp + nt * 8 + 2 * t;
        const float b0 = bias[n], b1 = bias[n + 1];
        #pragma unroll
        for (int mt = 0; mt < 4; ++mt) {
            const int m = m0 + a_warp + mt * 16 + g;
            float2 lo = make_float2(acc[mt][nt][0] + b0, acc[mt][nt][1] + b1);
            float2 hi = make_float2(acc[mt][nt][2] + b0, acc[mt][nt][3] + b1);
            *reinterpret_cast<float2*>(out + (size_t)m * OUTF + n) = lo;
            *reinterpret_cast<float2*>(out + (size_t)(m + 8) * OUTF + n) = hi;
        }
    }
}

// ---------------- launch ----------------
extern "C" void kernel_launch(void* const* d_in, const int* in_sizes, int n_in,
                              void* d_out, int out_size)
{
    const float* x = (const float*)d_in[0];   // [512, 4096]
    const float* U = (const float*)d_in[1];   // [4096*4096, 4]
    const float* q = (const float*)d_in[2];   // [4]
    const float* b = (const float*)d_in[3];   // [4096]
    const int*   e = (const int*)d_in[4];     // exponent scalar

    cudaFuncSetAttribute(gemm_tf32_kernel,
                         cudaFuncAttributeMaxDynamicSharedMemorySize, SMEM_BYTES);

    prep_w_kernel<<<16384, 256>>>((const float4*)U, q, e);
    round_x_kernel<<<2048, 256>>>((const float4*)x);
    gemm_tf32_kernel<<<dim3(OUTF / TN, BATCH / TM), 256, SMEM_BYTES>>>(b, (float*)d_out);
}